// round 3
// baseline (speedup 1.0000x reference)
#include <cuda_runtime.h>

#define MT 64      // rows per block
#define HH 256     // hidden dim
#define RR 32      // rank
#define HSTR 260   // padded row stride for h in shared (kills bank conflicts)

__device__ __forceinline__ float tanh_fast(float v) {
    // tanh(x) = 1 - 2/(exp(2x)+1); __expf is MUFU-based, abs err ~1e-7
    float e = __expf(2.0f * v);
    return 1.0f - __fdividef(2.0f, e + 1.0f);
}

extern __shared__ float smem[];

__global__ void __launch_bounds__(256, 2) pinn_kernel(
    const float* __restrict__ gx, const float* __restrict__ gt,
    const float* __restrict__ start_w, const float* __restrict__ start_b,
    const float* __restrict__ end_w, const float* __restrict__ end_b,
    const float* __restrict__ col0, const float* __restrict__ col1,
    const float* __restrict__ col2, const float* __restrict__ row0,
    const float* __restrict__ row1, const float* __restrict__ row2,
    const float* __restrict__ al0, const float* __restrict__ al1,
    const float* __restrict__ al2,
    float* __restrict__ out)
{
    float* h  = smem;                    // MT * HSTR
    float* u  = smem + MT * HSTR;        // MT * RR
    float* xs = u + MT * RR;             // MT
    float* ts = xs + MT;                 // MT

    const int tid  = threadIdx.x;
    const int base = blockIdx.x * MT;

    if (tid < MT)            xs[tid]      = gx[base + tid];
    else if (tid < 2 * MT)   ts[tid - MT] = gt[base + (tid - MT)];

    // ---- Phase A: h = tanh([x,t] @ start_w.T + start_b) ----
    const int j = tid;                       // thread owns hidden index j
    const float w0 = start_w[2 * j];
    const float w1 = start_w[2 * j + 1];
    const float sb = start_b[j];
    __syncthreads();

    #pragma unroll 4
    for (int m = 0; m < MT; m++) {
        h[m * HSTR + j] = tanh_fast(fmaf(xs[m], w0, fmaf(ts[m], w1, sb)));
    }
    __syncthreads();

    const int r  = tid & 31;   // rank index (lane)
    const int mb = tid >> 5;   // warp -> row group of 8

    #pragma unroll
    for (int blk = 0; blk < 3; blk++) {
        const float* cw = (blk == 0) ? col0 : (blk == 1) ? col1 : col2;
        const float* rw = (blk == 0) ? row0 : (blk == 1) ? row1 : row2;
        const float* av = (blk == 0) ? al0 : (blk == 1) ? al1 : al2;

        // ---- Phase B: u[m][r] = alpha[r] * sum_j h[m][j] * col[j][r] ----
        float acc[8];
        #pragma unroll
        for (int mm = 0; mm < 8; mm++) acc[mm] = 0.0f;

        #pragma unroll 2
        for (int jj = 0; jj < HH; jj += 4) {
            const float c0 = cw[(jj + 0) * RR + r];   // coalesced, L1-hot
            const float c1 = cw[(jj + 1) * RR + r];
            const float c2 = cw[(jj + 2) * RR + r];
            const float c3 = cw[(jj + 3) * RR + r];
            #pragma unroll
            for (int mm = 0; mm < 8; mm++) {
                const float4 hv = *(const float4*)(h + (mb * 8 + mm) * HSTR + jj); // broadcast
                float a = acc[mm];
                a = fmaf(hv.x, c0, a);
                a = fmaf(hv.y, c1, a);
                a = fmaf(hv.z, c2, a);
                a = fmaf(hv.w, c3, a);
                acc[mm] = a;
            }
        }
        const float alv = av[r];
        #pragma unroll
        for (int mm = 0; mm < 8; mm++) u[(mb * 8 + mm) * RR + r] = acc[mm] * alv;
        __syncthreads();

        // ---- Phase C: h[m][j] = tanh(sum_r u[m][r] * row[j][r]) ----
        float rwv[RR];
        #pragma unroll
        for (int rr = 0; rr < RR; rr += 4) {
            const float4 v = *(const float4*)(rw + j * RR + rr);  // coalesced 128B/warp
            rwv[rr + 0] = v.x; rwv[rr + 1] = v.y;
            rwv[rr + 2] = v.z; rwv[rr + 3] = v.w;
        }
        #pragma unroll 2
        for (int m0 = 0; m0 < MT; m0 += 4) {
            float b0 = 0.f, b1 = 0.f, b2 = 0.f, b3 = 0.f;
            #pragma unroll
            for (int rr = 0; rr < RR; rr += 4) {
                const float4 u0 = *(const float4*)(u + (m0 + 0) * RR + rr); // broadcast
                const float4 u1 = *(const float4*)(u + (m0 + 1) * RR + rr);
                const float4 u2 = *(const float4*)(u + (m0 + 2) * RR + rr);
                const float4 u3 = *(const float4*)(u + (m0 + 3) * RR + rr);
                b0 = fmaf(u0.x, rwv[rr], b0); b0 = fmaf(u0.y, rwv[rr+1], b0);
                b0 = fmaf(u0.z, rwv[rr+2], b0); b0 = fmaf(u0.w, rwv[rr+3], b0);
                b1 = fmaf(u1.x, rwv[rr], b1); b1 = fmaf(u1.y, rwv[rr+1], b1);
                b1 = fmaf(u1.z, rwv[rr+2], b1); b1 = fmaf(u1.w, rwv[rr+3], b1);
                b2 = fmaf(u2.x, rwv[rr], b2); b2 = fmaf(u2.y, rwv[rr+1], b2);
                b2 = fmaf(u2.z, rwv[rr+2], b2); b2 = fmaf(u2.w, rwv[rr+3], b2);
                b3 = fmaf(u3.x, rwv[rr], b3); b3 = fmaf(u3.y, rwv[rr+1], b3);
                b3 = fmaf(u3.z, rwv[rr+2], b3); b3 = fmaf(u3.w, rwv[rr+3], b3);
            }
            h[(m0 + 0) * HSTR + j] = tanh_fast(b0);  // conflict-free STS.32
            h[(m0 + 1) * HSTR + j] = tanh_fast(b1);
            h[(m0 + 2) * HSTR + j] = tanh_fast(b2);
            h[(m0 + 3) * HSTR + j] = tanh_fast(b3);
        }
        __syncthreads();
    }

    // ---- Phase D: out[m] = h[m] . end_w + end_b  (4 threads per row) ----
    const int m = tid >> 2;
    const int q = tid & 3;
    float s = 0.0f;
    #pragma unroll
    for (int jo = 0; jo < 64; jo += 4) {
        const int jj = q * 64 + jo;
        const float4 hv = *(const float4*)(h + m * HSTR + jj);
        const float4 wv = *(const float4*)(end_w + jj);
        s = fmaf(hv.x, wv.x, s);
        s = fmaf(hv.y, wv.y, s);
        s = fmaf(hv.z, wv.z, s);
        s = fmaf(hv.w, wv.w, s);
    }
    s += __shfl_xor_sync(0xffffffffu, s, 1);
    s += __shfl_xor_sync(0xffffffffu, s, 2);
    if (q == 0) out[base + m] = s + end_b[0];
}

extern "C" void kernel_launch(void* const* d_in, const int* in_sizes, int n_in,
                              void* d_out, int out_size) {
    const float* x  = (const float*)d_in[0];
    const float* t  = (const float*)d_in[1];
    const float* sw = (const float*)d_in[2];
    const float* sb = (const float*)d_in[3];
    const float* ew = (const float*)d_in[4];
    const float* eb = (const float*)d_in[5];
    const float* c0 = (const float*)d_in[6];
    const float* c1 = (const float*)d_in[7];
    const float* c2 = (const float*)d_in[8];
    const float* r0 = (const float*)d_in[9];
    const float* r1 = (const float*)d_in[10];
    const float* r2 = (const float*)d_in[11];
    const float* a0 = (const float*)d_in[12];
    const float* a1 = (const float*)d_in[13];
    const float* a2 = (const float*)d_in[14];
    float* out = (float*)d_out;

    const int N = in_sizes[0];
    const int smem_bytes = (MT * HSTR + MT * RR + 2 * MT) * (int)sizeof(float);
    cudaFuncSetAttribute(pinn_kernel, cudaFuncAttributeMaxDynamicSharedMemorySize,
                         smem_bytes);
    pinn_kernel<<<N / MT, 256, smem_bytes>>>(x, t, sw, sb, ew, eb,
                                             c0, c1, c2, r0, r1, r2,
                                             a0, a1, a2, out);
}

// round 4
// speedup vs baseline: 1.0015x; 1.0015x over previous
#include <cuda_runtime.h>

#define MT 64      // rows per block
#define HH 256     // hidden dim
#define RR 32      // rank
#define HSTR 260   // padded row stride for h in shared (kills bank conflicts)

__device__ __forceinline__ float tanh_fast(float v) {
    // tanh(x) = 1 - 2/(exp(2x)+1); __expf is MUFU-based, abs err ~1e-7
    float e = __expf(2.0f * v);
    return 1.0f - __fdividef(2.0f, e + 1.0f);
}

extern __shared__ float smem[];

__global__ void __launch_bounds__(256, 2) pinn_kernel(
    const float* __restrict__ gx, const float* __restrict__ gt,
    const float* __restrict__ start_w, const float* __restrict__ start_b,
    const float* __restrict__ end_w, const float* __restrict__ end_b,
    const float* __restrict__ col0, const float* __restrict__ col1,
    const float* __restrict__ col2, const float* __restrict__ row0,
    const float* __restrict__ row1, const float* __restrict__ row2,
    const float* __restrict__ al0, const float* __restrict__ al1,
    const float* __restrict__ al2,
    float* __restrict__ out)
{
    float* h  = smem;                    // MT * HSTR
    float* u  = smem + MT * HSTR;        // MT * RR
    float* xs = u + MT * RR;             // MT
    float* ts = xs + MT;                 // MT

    const int tid  = threadIdx.x;
    const int base = blockIdx.x * MT;

    if (tid < MT)            xs[tid]      = gx[base + tid];
    else if (tid < 2 * MT)   ts[tid - MT] = gt[base + (tid - MT)];

    // ---- Phase A: h = tanh([x,t] @ start_w.T + start_b) ----
    const int j = tid;                       // thread owns hidden index j
    const float w0 = start_w[2 * j];
    const float w1 = start_w[2 * j + 1];
    const float sb = start_b[j];
    __syncthreads();

    #pragma unroll 4
    for (int m = 0; m < MT; m++) {
        h[m * HSTR + j] = tanh_fast(fmaf(xs[m], w0, fmaf(ts[m], w1, sb)));
    }
    __syncthreads();

    const int r  = tid & 31;   // rank index (lane)
    const int mb = tid >> 5;   // warp -> row group of 8

    #pragma unroll
    for (int blk = 0; blk < 3; blk++) {
        const float* cw = (blk == 0) ? col0 : (blk == 1) ? col1 : col2;
        const float* rw = (blk == 0) ? row0 : (blk == 1) ? row1 : row2;
        const float* av = (blk == 0) ? al0 : (blk == 1) ? al1 : al2;

        // ---- Phase B: u[m][r] = alpha[r] * sum_j h[m][j] * col[j][r] ----
        float acc[8];
        #pragma unroll
        for (int mm = 0; mm < 8; mm++) acc[mm] = 0.0f;

        #pragma unroll 2
        for (int jj = 0; jj < HH; jj += 4) {
            const float c0 = cw[(jj + 0) * RR + r];   // coalesced, L1-hot
            const float c1 = cw[(jj + 1) * RR + r];
            const float c2 = cw[(jj + 2) * RR + r];
            const float c3 = cw[(jj + 3) * RR + r];
            #pragma unroll
            for (int mm = 0; mm < 8; mm++) {
                const float4 hv = *(const float4*)(h + (mb * 8 + mm) * HSTR + jj); // broadcast
                float a = acc[mm];
                a = fmaf(hv.x, c0, a);
                a = fmaf(hv.y, c1, a);
                a = fmaf(hv.z, c2, a);
                a = fmaf(hv.w, c3, a);
                acc[mm] = a;
            }
        }
        const float alv = av[r];
        #pragma unroll
        for (int mm = 0; mm < 8; mm++) u[(mb * 8 + mm) * RR + r] = acc[mm] * alv;
        __syncthreads();

        // ---- Phase C: h[m][j] = tanh(sum_r u[m][r] * row[j][r]) ----
        float rwv[RR];
        #pragma unroll
        for (int rr = 0; rr < RR; rr += 4) {
            const float4 v = *(const float4*)(rw + j * RR + rr);  // coalesced 128B/warp
            rwv[rr + 0] = v.x; rwv[rr + 1] = v.y;
            rwv[rr + 2] = v.z; rwv[rr + 3] = v.w;
        }
        #pragma unroll 2
        for (int m0 = 0; m0 < MT; m0 += 4) {
            float b0 = 0.f, b1 = 0.f, b2 = 0.f, b3 = 0.f;
            #pragma unroll
            for (int rr = 0; rr < RR; rr += 4) {
                const float4 u0 = *(const float4*)(u + (m0 + 0) * RR + rr); // broadcast
                const float4 u1 = *(const float4*)(u + (m0 + 1) * RR + rr);
                const float4 u2 = *(const float4*)(u + (m0 + 2) * RR + rr);
                const float4 u3 = *(const float4*)(u + (m0 + 3) * RR + rr);
                b0 = fmaf(u0.x, rwv[rr], b0); b0 = fmaf(u0.y, rwv[rr+1], b0);
                b0 = fmaf(u0.z, rwv[rr+2], b0); b0 = fmaf(u0.w, rwv[rr+3], b0);
                b1 = fmaf(u1.x, rwv[rr], b1); b1 = fmaf(u1.y, rwv[rr+1], b1);
                b1 = fmaf(u1.z, rwv[rr+2], b1); b1 = fmaf(u1.w, rwv[rr+3], b1);
                b2 = fmaf(u2.x, rwv[rr], b2); b2 = fmaf(u2.y, rwv[rr+1], b2);
                b2 = fmaf(u2.z, rwv[rr+2], b2); b2 = fmaf(u2.w, rwv[rr+3], b2);
                b3 = fmaf(u3.x, rwv[rr], b3); b3 = fmaf(u3.y, rwv[rr+1], b3);
                b3 = fmaf(u3.z, rwv[rr+2], b3); b3 = fmaf(u3.w, rwv[rr+3], b3);
            }
            h[(m0 + 0) * HSTR + j] = tanh_fast(b0);  // conflict-free STS.32
            h[(m0 + 1) * HSTR + j] = tanh_fast(b1);
            h[(m0 + 2) * HSTR + j] = tanh_fast(b2);
            h[(m0 + 3) * HSTR + j] = tanh_fast(b3);
        }
        __syncthreads();
    }

    // ---- Phase D: out[m] = h[m] . end_w + end_b  (4 threads per row) ----
    const int m = tid >> 2;
    const int q = tid & 3;
    float s = 0.0f;
    #pragma unroll
    for (int jo = 0; jo < 64; jo += 4) {
        const int jj = q * 64 + jo;
        const float4 hv = *(const float4*)(h + m * HSTR + jj);
        const float4 wv = *(const float4*)(end_w + jj);
        s = fmaf(hv.x, wv.x, s);
        s = fmaf(hv.y, wv.y, s);
        s = fmaf(hv.z, wv.z, s);
        s = fmaf(hv.w, wv.w, s);
    }
    s += __shfl_xor_sync(0xffffffffu, s, 1);
    s += __shfl_xor_sync(0xffffffffu, s, 2);
    if (q == 0) out[base + m] = s + end_b[0];
}

extern "C" void kernel_launch(void* const* d_in, const int* in_sizes, int n_in,
                              void* d_out, int out_size) {
    const float* x  = (const float*)d_in[0];
    const float* t  = (const float*)d_in[1];
    const float* sw = (const float*)d_in[2];
    const float* sb = (const float*)d_in[3];
    const float* ew = (const float*)d_in[4];
    const float* eb = (const float*)d_in[5];
    const float* c0 = (const float*)d_in[6];
    const float* c1 = (const float*)d_in[7];
    const float* c2 = (const float*)d_in[8];
    const float* r0 = (const float*)d_in[9];
    const float* r1 = (const float*)d_in[10];
    const float* r2 = (const float*)d_in[11];
    const float* a0 = (const float*)d_in[12];
    const float* a1 = (const float*)d_in[13];
    const float* a2 = (const float*)d_in[14];
    float* out = (float*)d_out;

    const int N = in_sizes[0];
    const int smem_bytes = (MT * HSTR + MT * RR + 2 * MT) * (int)sizeof(float);
    cudaFuncSetAttribute(pinn_kernel, cudaFuncAttributeMaxDynamicSharedMemorySize,
                         smem_bytes);
    pinn_kernel<<<N / MT, 256, smem_bytes>>>(x, t, sw, sb, ew, eb,
                                             c0, c1, c2, r0, r1, r2,
                                             a0, a1, a2, out);
}

// round 5
// speedup vs baseline: 1.0866x; 1.0850x over previous
#include <cuda_runtime.h>

#define MT 64      // rows per block
#define HH 256     // hidden dim
#define RR 32      // rank
#define HSTR 260   // padded row stride for h in shared (16B-aligned, kills conflicts)

// Packed, alpha-folded col weights: [blk][k/4][r] = (col[4k..4k+3][r] * alpha[r])
__device__ float4 g_cpack[3][HH / 4][RR];

__device__ __forceinline__ float tanh_fast(float v) {
    float e = __expf(2.0f * v);
    return 1.0f - __fdividef(2.0f, e + 1.0f);
}

// packed dual-fp32 FMA (sm_103a FFMA2): acc.lo += a.lo*b.lo; acc.hi += a.hi*b.hi
#define FMA2(acc, a, b) \
    asm("fma.rn.f32x2 %0, %1, %2, %0;" : "+l"(acc) : "l"(a), "l"(b))

__device__ __forceinline__ float hadd2(unsigned long long v) {
    float lo, hi;
    asm("mov.b64 {%0, %1}, %2;" : "=f"(lo), "=f"(hi) : "l"(v));
    return lo + hi;
}

__global__ void pack_kernel(const float* __restrict__ col0, const float* __restrict__ col1,
                            const float* __restrict__ col2, const float* __restrict__ al0,
                            const float* __restrict__ al1, const float* __restrict__ al2)
{
    int idx = blockIdx.x * blockDim.x + threadIdx.x;   // over 3 * 64 * 32
    if (idx >= 3 * (HH / 4) * RR) return;
    int b  = idx / ((HH / 4) * RR);
    int k4 = (idx / RR) % (HH / 4);
    int r  = idx % RR;
    const float* c = (b == 0) ? col0 : (b == 1) ? col1 : col2;
    const float* a = (b == 0) ? al0 : (b == 1) ? al1 : al2;
    const float av = a[r];
    g_cpack[b][k4][r] = make_float4(c[(4 * k4 + 0) * RR + r] * av,
                                    c[(4 * k4 + 1) * RR + r] * av,
                                    c[(4 * k4 + 2) * RR + r] * av,
                                    c[(4 * k4 + 3) * RR + r] * av);
}

extern __shared__ float smem[];

__global__ void __launch_bounds__(256, 2) pinn_kernel(
    const float* __restrict__ gx, const float* __restrict__ gt,
    const float* __restrict__ start_w, const float* __restrict__ start_b,
    const float* __restrict__ end_w, const float* __restrict__ end_b,
    const float* __restrict__ row0, const float* __restrict__ row1,
    const float* __restrict__ row2,
    float* __restrict__ out)
{
    float* h  = smem;                    // MT * HSTR  (byte offset multiple of 16)
    float* u  = smem + MT * HSTR;        // MT * RR
    float* xs = u + MT * RR;             // MT
    float* ts = xs + MT;                 // MT

    const int tid  = threadIdx.x;
    const int base = blockIdx.x * MT;

    if (tid < MT)            xs[tid]      = gx[base + tid];
    else if (tid < 2 * MT)   ts[tid - MT] = gt[base + (tid - MT)];

    // ---- Phase A: h = tanh([x,t] @ start_w.T + start_b) ----
    const int j = tid;                       // thread owns hidden index j
    const float w0 = start_w[2 * j];
    const float w1 = start_w[2 * j + 1];
    const float sb = start_b[j];
    __syncthreads();

    #pragma unroll 4
    for (int m = 0; m < MT; m++) {
        h[m * HSTR + j] = tanh_fast(fmaf(xs[m], w0, fmaf(ts[m], w1, sb)));
    }
    __syncthreads();

    const int r  = tid & 31;   // rank index (lane)
    const int mb = tid >> 5;   // warp -> row group of 8

    #pragma unroll
    for (int blk = 0; blk < 3; blk++) {
        const float* rw = (blk == 0) ? row0 : (blk == 1) ? row1 : row2;
        const ulonglong2* cp =
            ((const ulonglong2*)g_cpack) + (size_t)blk * (HH / 4) * RR;

        // ---- Phase B: u[m][r] = sum_k h[m][k] * (col*alpha)[k][r]  (FMA2 over k-pairs)
        unsigned long long acc2[8];
        #pragma unroll
        for (int mm = 0; mm < 8; mm++) acc2[mm] = 0ull;

        #pragma unroll 2
        for (int k4 = 0; k4 < HH / 4; k4++) {
            const ulonglong2 cv = __ldg(&cp[k4 * RR + r]);   // 4 k-values for this r
            #pragma unroll
            for (int mm = 0; mm < 8; mm++) {
                const ulonglong2 hv =
                    *(const ulonglong2*)(h + (mb * 8 + mm) * HSTR + 4 * k4); // broadcast
                FMA2(acc2[mm], hv.x, cv.x);
                FMA2(acc2[mm], hv.y, cv.y);
            }
        }
        #pragma unroll
        for (int mm = 0; mm < 8; mm++)
            u[(mb * 8 + mm) * RR + r] = hadd2(acc2[mm]);
        __syncthreads();

        // ---- Phase C: h[m][j] = tanh(sum_r u[m][r] * row[j][r])  (FMA2 over r-pairs)
        unsigned long long rp[16];
        {
            const ulonglong2* rw2 = (const ulonglong2*)(rw + j * RR);
            #pragma unroll
            for (int i = 0; i < 8; i++) {
                const ulonglong2 t = __ldg(&rw2[i]);
                rp[2 * i]     = t.x;
                rp[2 * i + 1] = t.y;
            }
        }
        #pragma unroll 2
        for (int m0 = 0; m0 < MT; m0 += 4) {
            unsigned long long a0 = 0ull, a1 = 0ull, a2 = 0ull, a3 = 0ull;
            const ulonglong2* up0 = (const ulonglong2*)(u + (m0 + 0) * RR);
            const ulonglong2* up1 = (const ulonglong2*)(u + (m0 + 1) * RR);
            const ulonglong2* up2 = (const ulonglong2*)(u + (m0 + 2) * RR);
            const ulonglong2* up3 = (const ulonglong2*)(u + (m0 + 3) * RR);
            #pragma unroll
            for (int q = 0; q < 8; q++) {                 // 4 r-values per q
                const ulonglong2 v0 = up0[q];             // broadcast LDS.128
                const ulonglong2 v1 = up1[q];
                const ulonglong2 v2 = up2[q];
                const ulonglong2 v3 = up3[q];
                FMA2(a0, v0.x, rp[2 * q]); FMA2(a0, v0.y, rp[2 * q + 1]);
                FMA2(a1, v1.x, rp[2 * q]); FMA2(a1, v1.y, rp[2 * q + 1]);
                FMA2(a2, v2.x, rp[2 * q]); FMA2(a2, v2.y, rp[2 * q + 1]);
                FMA2(a3, v3.x, rp[2 * q]); FMA2(a3, v3.y, rp[2 * q + 1]);
            }
            h[(m0 + 0) * HSTR + j] = tanh_fast(hadd2(a0));
            h[(m0 + 1) * HSTR + j] = tanh_fast(hadd2(a1));
            h[(m0 + 2) * HSTR + j] = tanh_fast(hadd2(a2));
            h[(m0 + 3) * HSTR + j] = tanh_fast(hadd2(a3));
        }
        __syncthreads();
    }

    // ---- Phase D: out[m] = h[m] . end_w + end_b  (4 threads per row) ----
    const int m = tid >> 2;
    const int q = tid & 3;
    float s = 0.0f;
    #pragma unroll
    for (int jo = 0; jo < 64; jo += 4) {
        const int jj = q * 64 + jo;
        const float4 hv = *(const float4*)(h + m * HSTR + jj);
        const float4 wv = *(const float4*)(end_w + jj);
        s = fmaf(hv.x, wv.x, s);
        s = fmaf(hv.y, wv.y, s);
        s = fmaf(hv.z, wv.z, s);
        s = fmaf(hv.w, wv.w, s);
    }
    s += __shfl_xor_sync(0xffffffffu, s, 1);
    s += __shfl_xor_sync(0xffffffffu, s, 2);
    if (q == 0) out[base + m] = s + end_b[0];
}

extern "C" void kernel_launch(void* const* d_in, const int* in_sizes, int n_in,
                              void* d_out, int out_size) {
    const float* x  = (const float*)d_in[0];
    const float* t  = (const float*)d_in[1];
    const float* sw = (const float*)d_in[2];
    const float* sb = (const float*)d_in[3];
    const float* ew = (const float*)d_in[4];
    const float* eb = (const float*)d_in[5];
    const float* c0 = (const float*)d_in[6];
    const float* c1 = (const float*)d_in[7];
    const float* c2 = (const float*)d_in[8];
    const float* r0 = (const float*)d_in[9];
    const float* r1 = (const float*)d_in[10];
    const float* r2 = (const float*)d_in[11];
    const float* a0 = (const float*)d_in[12];
    const float* a1 = (const float*)d_in[13];
    const float* a2 = (const float*)d_in[14];
    float* out = (float*)d_out;

    const int N = in_sizes[0];

    // pre-pack alpha-folded col weights into __device__ scratch
    pack_kernel<<<(3 * (HH / 4) * RR + 255) / 256, 256>>>(c0, c1, c2, a0, a1, a2);

    const int smem_bytes = (MT * HSTR + MT * RR + 2 * MT) * (int)sizeof(float);
    cudaFuncSetAttribute(pinn_kernel, cudaFuncAttributeMaxDynamicSharedMemorySize,
                         smem_bytes);
    pinn_kernel<<<N / MT, 256, smem_bytes>>>(x, t, sw, sb, ew, eb,
                                             r0, r1, r2, out);
}

// round 7
// speedup vs baseline: 1.0900x; 1.0031x over previous
#include <cuda_runtime.h>

#define MT 64      // rows per block
#define HH 256     // hidden dim
#define RR 32      // rank
#define HSTR 260   // padded row stride for h in shared (16B-aligned, kills conflicts)

// Packed, alpha-folded col weights: [blk][k/4][r] = (col[4k..4k+3][r] * alpha[r])
__device__ float4 g_cpack[3][HH / 4][RR];

__device__ __forceinline__ float tanh_fast(float v) {
    float e = __expf(2.0f * v);
    return 1.0f - __fdividef(2.0f, e + 1.0f);
}

// packed dual-fp32 FMA (sm_103a FFMA2): acc.lo += a.lo*b.lo; acc.hi += a.hi*b.hi
#define FMA2(acc, a, b) \
    asm("fma.rn.f32x2 %0, %1, %2, %0;" : "+l"(acc) : "l"(a), "l"(b))

__device__ __forceinline__ float hadd2(unsigned long long v) {
    float lo, hi;
    asm("mov.b64 {%0, %1}, %2;" : "=f"(lo), "=f"(hi) : "l"(v));
    return lo + hi;
}

__global__ void pack_kernel(const float* __restrict__ col0, const float* __restrict__ col1,
                            const float* __restrict__ col2, const float* __restrict__ al0,
                            const float* __restrict__ al1, const float* __restrict__ al2)
{
    int idx = blockIdx.x * blockDim.x + threadIdx.x;   // over 3 * 64 * 32
    if (idx >= 3 * (HH / 4) * RR) return;
    int b  = idx / ((HH / 4) * RR);
    int k4 = (idx / RR) % (HH / 4);
    int r  = idx % RR;
    const float* c = (b == 0) ? col0 : (b == 1) ? col1 : col2;
    const float* a = (b == 0) ? al0 : (b == 1) ? al1 : al2;
    const float av = a[r];
    g_cpack[b][k4][r] = make_float4(c[(4 * k4 + 0) * RR + r] * av,
                                    c[(4 * k4 + 1) * RR + r] * av,
                                    c[(4 * k4 + 2) * RR + r] * av,
                                    c[(4 * k4 + 3) * RR + r] * av);
}

extern __shared__ float smem[];

__global__ void __launch_bounds__(256, 2) pinn_kernel(
    const float* __restrict__ gx, const float* __restrict__ gt,
    const float* __restrict__ start_w, const float* __restrict__ start_b,
    const float* __restrict__ end_w, const float* __restrict__ end_b,
    const float* __restrict__ row0, const float* __restrict__ row1,
    const float* __restrict__ row2,
    float* __restrict__ out)
{
    float* h  = smem;                    // MT * HSTR  (byte offset multiple of 16)
    float* u  = smem + MT * HSTR;        // MT * RR
    float* xs = u + MT * RR;             // MT
    float* ts = xs + MT;                 // MT

    const int tid  = threadIdx.x;
    const int base = blockIdx.x * MT;

    if (tid < MT)            xs[tid]      = gx[base + tid];
    else if (tid < 2 * MT)   ts[tid - MT] = gt[base + (tid - MT)];

    // ---- Phase A: h = tanh([x,t] @ start_w.T + start_b) ----
    const int j = tid;                       // thread owns hidden index j
    const float w0 = start_w[2 * j];
    const float w1 = start_w[2 * j + 1];
    const float sb = start_b[j];
    __syncthreads();

    #pragma unroll 4
    for (int m = 0; m < MT; m++) {
        h[m * HSTR + j] = tanh_fast(fmaf(xs[m], w0, fmaf(ts[m], w1, sb)));
    }
    __syncthreads();

    const int r  = tid & 31;   // rank index (lane)
    const int mb = tid >> 5;   // warp -> row group of 8

    #pragma unroll
    for (int blk = 0; blk < 3; blk++) {
        const float* rw = (blk == 0) ? row0 : (blk == 1) ? row1 : row2;
        const ulonglong2* cp =
            ((const ulonglong2*)g_cpack) + (size_t)blk * (HH / 4) * RR;

        // ---- Phase B: u[m][r] = sum_k h[m][k] * (col*alpha)[k][r]  (FMA2 over k-pairs)
        unsigned long long acc2[8];
        #pragma unroll
        for (int mm = 0; mm < 8; mm++) acc2[mm] = 0ull;

        #pragma unroll 2
        for (int k4 = 0; k4 < HH / 4; k4++) {
            const ulonglong2 cv = __ldg(&cp[k4 * RR + r]);   // 4 k-values for this r
            #pragma unroll
            for (int mm = 0; mm < 8; mm++) {
                const ulonglong2 hv =
                    *(const ulonglong2*)(h + (mb * 8 + mm) * HSTR + 4 * k4); // broadcast
                FMA2(acc2[mm], hv.x, cv.x);
                FMA2(acc2[mm], hv.y, cv.y);
            }
        }
        #pragma unroll
        for (int mm = 0; mm < 8; mm++)
            u[(mb * 8 + mm) * RR + r] = hadd2(acc2[mm]);
        __syncthreads();

        // ---- Phase C: h[m][j] = tanh(sum_r u[m][r] * row[j][r])  (FMA2 over r-pairs)
        unsigned long long rp[16];
        {
            const ulonglong2* rw2 = (const ulonglong2*)(rw + j * RR);
            #pragma unroll
            for (int i = 0; i < 8; i++) {
                const ulonglong2 t = __ldg(&rw2[i]);
                rp[2 * i]     = t.x;
                rp[2 * i + 1] = t.y;
            }
        }
        #pragma unroll 2
        for (int m0 = 0; m0 < MT; m0 += 4) {
            unsigned long long a0 = 0ull, a1 = 0ull, a2 = 0ull, a3 = 0ull;
            const ulonglong2* up0 = (const ulonglong2*)(u + (m0 + 0) * RR);
            const ulonglong2* up1 = (const ulonglong2*)(u + (m0 + 1) * RR);
            const ulonglong2* up2 = (const ulonglong2*)(u + (m0 + 2) * RR);
            const ulonglong2* up3 = (const ulonglong2*)(u + (m0 + 3) * RR);
            #pragma unroll
            for (int q = 0; q < 8; q++) {                 // 4 r-values per q
                const ulonglong2 v0 = up0[q];             // broadcast LDS.128
                const ulonglong2 v1 = up1[q];
                const ulonglong2 v2 = up2[q];
                const ulonglong2 v3 = up3[q];
                FMA2(a0, v0.x, rp[2 * q]); FMA2(a0, v0.y, rp[2 * q + 1]);
                FMA2(a1, v1.x, rp[2 * q]); FMA2(a1, v1.y, rp[2 * q + 1]);
                FMA2(a2, v2.x, rp[2 * q]); FMA2(a2, v2.y, rp[2 * q + 1]);
                FMA2(a3, v3.x, rp[2 * q]); FMA2(a3, v3.y, rp[2 * q + 1]);
            }
            h[(m0 + 0) * HSTR + j] = tanh_fast(hadd2(a0));
            h[(m0 + 1) * HSTR + j] = tanh_fast(hadd2(a1));
            h[(m0 + 2) * HSTR + j] = tanh_fast(hadd2(a2));
            h[(m0 + 3) * HSTR + j] = tanh_fast(hadd2(a3));
        }
        __syncthreads();
    }

    // ---- Phase D: out[m] = h[m] . end_w + end_b  (4 threads per row) ----
    const int m = tid >> 2;
    const int q = tid & 3;
    float s = 0.0f;
    #pragma unroll
    for (int jo = 0; jo < 64; jo += 4) {
        const int jj = q * 64 + jo;
        const float4 hv = *(const float4*)(h + m * HSTR + jj);
        const float4 wv = *(const float4*)(end_w + jj);
        s = fmaf(hv.x, wv.x, s);
        s = fmaf(hv.y, wv.y, s);
        s = fmaf(hv.z, wv.z, s);
        s = fmaf(hv.w, wv.w, s);
    }
    s += __shfl_xor_sync(0xffffffffu, s, 1);
    s += __shfl_xor_sync(0xffffffffu, s, 2);
    if (q == 0) out[base + m] = s + end_b[0];
}

extern "C" void kernel_launch(void* const* d_in, const int* in_sizes, int n_in,
                              void* d_out, int out_size) {
    const float* x  = (const float*)d_in[0];
    const float* t  = (const float*)d_in[1];
    const float* sw = (const float*)d_in[2];
    const float* sb = (const float*)d_in[3];
    const float* ew = (const float*)d_in[4];
    const float* eb = (const float*)d_in[5];
    const float* c0 = (const float*)d_in[6];
    const float* c1 = (const float*)d_in[7];
    const float* c2 = (const float*)d_in[8];
    const float* r0 = (const float*)d_in[9];
    const float* r1 = (const float*)d_in[10];
    const float* r2 = (const float*)d_in[11];
    const float* a0 = (const float*)d_in[12];
    const float* a1 = (const float*)d_in[13];
    const float* a2 = (const float*)d_in[14];
    float* out = (float*)d_out;

    const int N = in_sizes[0];

    // pre-pack alpha-folded col weights into __device__ scratch
    pack_kernel<<<(3 * (HH / 4) * RR + 255) / 256, 256>>>(c0, c1, c2, a0, a1, a2);

    const int smem_bytes = (MT * HSTR + MT * RR + 2 * MT) * (int)sizeof(float);
    cudaFuncSetAttribute(pinn_kernel, cudaFuncAttributeMaxDynamicSharedMemorySize,
                         smem_bytes);
    pinn_kernel<<<N / MT, 256, smem_bytes>>>(x, t, sw, sb, ew, eb,
                                             r0, r1, r2, out);
}

// round 8
// speedup vs baseline: 1.0904x; 1.0004x over previous
#include <cuda_runtime.h>

#define MT 64      // rows per block
#define HH 256     // hidden dim
#define RR 32      // rank
#define HSTR 260   // padded row stride for h in shared (16B-aligned, kills conflicts)

// Packed, alpha-folded col weights: [blk][k/4][r] = (col[4k..4k+3][r] * alpha[r])
__device__ float4 g_cpack[3][HH / 4][RR];

__device__ __forceinline__ float tanh_fast(float v) {
    float e = __expf(2.0f * v);
    return 1.0f - __fdividef(2.0f, e + 1.0f);
}

// packed dual-fp32 FMA (sm_103a FFMA2): acc.lo += a.lo*b.lo; acc.hi += a.hi*b.hi
#define FMA2(acc, a, b) \
    asm("fma.rn.f32x2 %0, %1, %2, %0;" : "+l"(acc) : "l"(a), "l"(b))

__device__ __forceinline__ float hadd2(unsigned long long v) {
    float lo, hi;
    asm("mov.b64 {%0, %1}, %2;" : "=f"(lo), "=f"(hi) : "l"(v));
    return lo + hi;
}

__global__ void pack_kernel(const float* __restrict__ col0, const float* __restrict__ col1,
                            const float* __restrict__ col2, const float* __restrict__ al0,
                            const float* __restrict__ al1, const float* __restrict__ al2)
{
    int idx = blockIdx.x * blockDim.x + threadIdx.x;   // over 3 * 64 * 32
    if (idx >= 3 * (HH / 4) * RR) return;
    int b  = idx / ((HH / 4) * RR);
    int k4 = (idx / RR) % (HH / 4);
    int r  = idx % RR;
    const float* c = (b == 0) ? col0 : (b == 1) ? col1 : col2;
    const float* a = (b == 0) ? al0 : (b == 1) ? al1 : al2;
    const float av = a[r];
    g_cpack[b][k4][r] = make_float4(c[(4 * k4 + 0) * RR + r] * av,
                                    c[(4 * k4 + 1) * RR + r] * av,
                                    c[(4 * k4 + 2) * RR + r] * av,
                                    c[(4 * k4 + 3) * RR + r] * av);
}

extern __shared__ float smem[];

__global__ void __launch_bounds__(256, 2) pinn_kernel(
    const float* __restrict__ gx, const float* __restrict__ gt,
    const float* __restrict__ start_w, const float* __restrict__ start_b,
    const float* __restrict__ end_w, const float* __restrict__ end_b,
    const float* __restrict__ row0, const float* __restrict__ row1,
    const float* __restrict__ row2,
    float* __restrict__ out)
{
    float* h  = smem;                    // MT * HSTR  (byte offset multiple of 16)
    float* u  = smem + MT * HSTR;        // MT * RR
    float* xs = u + MT * RR;             // MT
    float* ts = xs + MT;                 // MT

    const int tid  = threadIdx.x;
    const int base = blockIdx.x * MT;

    if (tid < MT)            xs[tid]      = gx[base + tid];
    else if (tid < 2 * MT)   ts[tid - MT] = gt[base + (tid - MT)];

    // ---- Phase A: h = tanh([x,t] @ start_w.T + start_b) ----
    const int j = tid;                       // thread owns hidden index j
    const float w0 = start_w[2 * j];
    const float w1 = start_w[2 * j + 1];
    const float sb = start_b[j];
    __syncthreads();

    #pragma unroll 4
    for (int m = 0; m < MT; m++) {
        h[m * HSTR + j] = tanh_fast(fmaf(xs[m], w0, fmaf(ts[m], w1, sb)));
    }
    __syncthreads();

    const int r  = tid & 31;   // rank index (lane)
    const int mb = tid >> 5;   // warp -> row group of 8

    #pragma unroll
    for (int blk = 0; blk < 3; blk++) {
        const float* rw = (blk == 0) ? row0 : (blk == 1) ? row1 : row2;
        const ulonglong2* cp =
            ((const ulonglong2*)g_cpack) + (size_t)blk * (HH / 4) * RR;

        // ---- Phase B: u[m][r] = sum_k h[m][k] * (col*alpha)[k][r]  (FMA2 over k-pairs)
        unsigned long long acc2[8];
        #pragma unroll
        for (int mm = 0; mm < 8; mm++) acc2[mm] = 0ull;

        #pragma unroll 2
        for (int k4 = 0; k4 < HH / 4; k4++) {
            const ulonglong2 cv = __ldg(&cp[k4 * RR + r]);   // 4 k-values for this r
            #pragma unroll
            for (int mm = 0; mm < 8; mm++) {
                const ulonglong2 hv =
                    *(const ulonglong2*)(h + (mb * 8 + mm) * HSTR + 4 * k4); // broadcast
                FMA2(acc2[mm], hv.x, cv.x);
                FMA2(acc2[mm], hv.y, cv.y);
            }
        }
        #pragma unroll
        for (int mm = 0; mm < 8; mm++)
            u[(mb * 8 + mm) * RR + r] = hadd2(acc2[mm]);
        __syncthreads();

        // ---- Phase C: h[m][j] = tanh(sum_r u[m][r] * row[j][r])  (FMA2 over r-pairs)
        unsigned long long rp[16];
        {
            const ulonglong2* rw2 = (const ulonglong2*)(rw + j * RR);
            #pragma unroll
            for (int i = 0; i < 8; i++) {
                const ulonglong2 t = __ldg(&rw2[i]);
                rp[2 * i]     = t.x;
                rp[2 * i + 1] = t.y;
            }
        }
        #pragma unroll 2
        for (int m0 = 0; m0 < MT; m0 += 4) {
            unsigned long long a0 = 0ull, a1 = 0ull, a2 = 0ull, a3 = 0ull;
            const ulonglong2* up0 = (const ulonglong2*)(u + (m0 + 0) * RR);
            const ulonglong2* up1 = (const ulonglong2*)(u + (m0 + 1) * RR);
            const ulonglong2* up2 = (const ulonglong2*)(u + (m0 + 2) * RR);
            const ulonglong2* up3 = (const ulonglong2*)(u + (m0 + 3) * RR);
            #pragma unroll
            for (int q = 0; q < 8; q++) {                 // 4 r-values per q
                const ulonglong2 v0 = up0[q];             // broadcast LDS.128
                const ulonglong2 v1 = up1[q];
                const ulonglong2 v2 = up2[q];
                const ulonglong2 v3 = up3[q];
                FMA2(a0, v0.x, rp[2 * q]); FMA2(a0, v0.y, rp[2 * q + 1]);
                FMA2(a1, v1.x, rp[2 * q]); FMA2(a1, v1.y, rp[2 * q + 1]);
                FMA2(a2, v2.x, rp[2 * q]); FMA2(a2, v2.y, rp[2 * q + 1]);
                FMA2(a3, v3.x, rp[2 * q]); FMA2(a3, v3.y, rp[2 * q + 1]);
            }
            h[(m0 + 0) * HSTR + j] = tanh_fast(hadd2(a0));
            h[(m0 + 1) * HSTR + j] = tanh_fast(hadd2(a1));
            h[(m0 + 2) * HSTR + j] = tanh_fast(hadd2(a2));
            h[(m0 + 3) * HSTR + j] = tanh_fast(hadd2(a3));
        }
        __syncthreads();
    }

    // ---- Phase D: out[m] = h[m] . end_w + end_b  (4 threads per row) ----
    const int m = tid >> 2;
    const int q = tid & 3;
    float s = 0.0f;
    #pragma unroll
    for (int jo = 0; jo < 64; jo += 4) {
        const int jj = q * 64 + jo;
        const float4 hv = *(const float4*)(h + m * HSTR + jj);
        const float4 wv = *(const float4*)(end_w + jj);
        s = fmaf(hv.x, wv.x, s);
        s = fmaf(hv.y, wv.y, s);
        s = fmaf(hv.z, wv.z, s);
        s = fmaf(hv.w, wv.w, s);
    }
    s += __shfl_xor_sync(0xffffffffu, s, 1);
    s += __shfl_xor_sync(0xffffffffu, s, 2);
    if (q == 0) out[base + m] = s + end_b[0];
}

extern "C" void kernel_launch(void* const* d_in, const int* in_sizes, int n_in,
                              void* d_out, int out_size) {
    const float* x  = (const float*)d_in[0];
    const float* t  = (const float*)d_in[1];
    const float* sw = (const float*)d_in[2];
    const float* sb = (const float*)d_in[3];
    const float* ew = (const float*)d_in[4];
    const float* eb = (const float*)d_in[5];
    const float* c0 = (const float*)d_in[6];
    const float* c1 = (const float*)d_in[7];
    const float* c2 = (const float*)d_in[8];
    const float* r0 = (const float*)d_in[9];
    const float* r1 = (const float*)d_in[10];
    const float* r2 = (const float*)d_in[11];
    const float* a0 = (const float*)d_in[12];
    const float* a1 = (const float*)d_in[13];
    const float* a2 = (const float*)d_in[14];
    float* out = (float*)d_out;

    const int N = in_sizes[0];

    // pre-pack alpha-folded col weights into __device__ scratch
    pack_kernel<<<(3 * (HH / 4) * RR + 255) / 256, 256>>>(c0, c1, c2, a0, a1, a2);

    const int smem_bytes = (MT * HSTR + MT * RR + 2 * MT) * (int)sizeof(float);
    cudaFuncSetAttribute(pinn_kernel, cudaFuncAttributeMaxDynamicSharedMemorySize,
                         smem_bytes);
    pinn_kernel<<<N / MT, 256, smem_bytes>>>(x, t, sw, sb, ew, eb,
                                             r0, r1, r2, out);
}